// round 1
// baseline (speedup 1.0000x reference)
#include <cuda_runtime.h>
#include <math.h>

#define T_NEWC 2048
#define HIDC   2048
#define NHC    16
#define KVHC   2
#define HDC    128
#define T_PASTC 2048
#define T_FULLC 4096
#define KVDC   256           // KVHC*HDC

#define OUT0   (T_NEWC*HIDC)                  // 4194304 floats: attention output
#define KOFF   OUT0                           // new_k: [2,4096,128]
#define VOFF   (OUT0 + KVHC*T_FULLC*HDC)      // new_v

// Scratch (static device globals; no allocation)
__device__ float g_q[T_NEWC*HIDC];       // [t][h*128+d]
__device__ float g_kn[T_NEWC*KVDC];      // [t][kh*128+d]
__device__ float g_vn[T_NEWC*KVDC];
__device__ float g_attn[T_NEWC*HIDC];    // [t][h*128+d]

// ---------------------------------------------------------------------------
// SGEMM: C[M,N] = A[M,K] @ W[N,K]^T + bias[N]   (fp32, 128x128x8 tiles)
// ---------------------------------------------------------------------------
__global__ __launch_bounds__(256) void sgemm_bias(
    const float* __restrict__ A, const float* __restrict__ W,
    const float* __restrict__ bias, float* __restrict__ C,
    int N, int K)
{
    __shared__ float As[8][128];
    __shared__ float Ws[8][128];
    const int bm = blockIdx.y * 128;
    const int bn = blockIdx.x * 128;
    const int tid = threadIdx.x;
    const int tx = tid & 15;      // 0..15 -> 8 cols each
    const int ty = tid >> 4;      // 0..15 -> 8 rows each
    const int lr = tid >> 1;      // 0..127
    const int lc = (tid & 1) << 2;// 0 or 4

    const float* Ap = A + (size_t)(bm + lr) * K + lc;
    const float* Wp = W + (size_t)(bn + lr) * K + lc;

    float acc[8][8];
    #pragma unroll
    for (int i = 0; i < 8; i++)
        #pragma unroll
        for (int j = 0; j < 8; j++) acc[i][j] = 0.f;

    for (int k0 = 0; k0 < K; k0 += 8) {
        float4 a4 = *(const float4*)(Ap + k0);
        float4 w4 = *(const float4*)(Wp + k0);
        As[lc+0][lr] = a4.x; As[lc+1][lr] = a4.y;
        As[lc+2][lr] = a4.z; As[lc+3][lr] = a4.w;
        Ws[lc+0][lr] = w4.x; Ws[lc+1][lr] = w4.y;
        Ws[lc+2][lr] = w4.z; Ws[lc+3][lr] = w4.w;
        __syncthreads();
        #pragma unroll
        for (int k = 0; k < 8; k++) {
            float ar[8], br[8];
            *(float4*)&ar[0] = *(const float4*)&As[k][ty*8];
            *(float4*)&ar[4] = *(const float4*)&As[k][ty*8+4];
            *(float4*)&br[0] = *(const float4*)&Ws[k][tx*8];
            *(float4*)&br[4] = *(const float4*)&Ws[k][tx*8+4];
            #pragma unroll
            for (int i = 0; i < 8; i++)
                #pragma unroll
                for (int j = 0; j < 8; j++)
                    acc[i][j] += ar[i] * br[j];
        }
        __syncthreads();
    }

    #pragma unroll
    for (int i = 0; i < 8; i++) {
        const int row = bm + ty*8 + i;
        #pragma unroll
        for (int j = 0; j < 8; j += 4) {
            const int col = bn + tx*8 + j;
            float4 o;
            o.x = acc[i][j+0] + bias[col+0];
            o.y = acc[i][j+1] + bias[col+1];
            o.z = acc[i][j+2] + bias[col+2];
            o.w = acc[i][j+3] + bias[col+3];
            *(float4*)(C + (size_t)row * N + col) = o;
        }
    }
}

// ---------------------------------------------------------------------------
// Concat KV cache: out[KOFF..] = new_k [2,4096,128], out[VOFF..] = new_v
// ---------------------------------------------------------------------------
__global__ void concat_kv(const float* __restrict__ pk,
                          const float* __restrict__ pv,
                          float* __restrict__ out)
{
    int idx = blockIdx.x * blockDim.x + threadIdx.x;
    const int total = KVHC * T_FULLC * HDC;   // 1,048,576
    if (idx >= total) return;
    int d = idx & (HDC - 1);
    int t = (idx >> 7) & (T_FULLC - 1);
    int h = idx >> 19;                        // / (4096*128)
    float vk, vv;
    if (t < T_PASTC) {
        int src = (h * T_PASTC + t) * HDC + d;
        vk = pk[src];
        vv = pv[src];
    } else {
        int src = (t - T_PASTC) * KVDC + h * HDC + d;
        vk = g_kn[src];
        vv = g_vn[src];
    }
    out[KOFF + idx] = vk;
    out[VOFF + idx] = vv;
}

// ---------------------------------------------------------------------------
// Flash attention (fp32, causal, GQA rep=8). BM=64 q rows, BN=64 keys/tile.
// Grid: (32 q-tiles, 16 heads). 256 threads.
// ---------------------------------------------------------------------------
#define FBM 64
#define FBN 64
#define ATT_SCALE 0.08838834764831845f  // 1/sqrt(128)

// dynamic smem layout (floats):
//   Qs [64][128]      8192
//   Ks [64][129]      8256
//   Vs [64][128]      8192
//   Ss [64][65]       4160
//   frow[64] lrow[64]  128
#define FSMEM_FLOATS (8192 + 8256 + 8192 + 4160 + 128)
#define FSMEM_BYTES  (FSMEM_FLOATS * 4)

__global__ __launch_bounds__(256, 2) void flash_attn(
    const float* __restrict__ Kc, const float* __restrict__ Vc)
{
    extern __shared__ float sm[];
    float* Qs   = sm;
    float* Ks   = Qs + 64*128;
    float* Vs   = Ks + 64*129;
    float* Ss   = Vs + 64*128;
    float* frow = Ss + 64*65;
    float* lrow = frow + 64;

    const int qi = blockIdx.x;          // 0..31
    const int h  = blockIdx.y;          // 0..15
    const int qbase = qi * FBM;
    const int kh = h >> 3;              // GQA: 8 q-heads per kv-head
    const int tid = threadIdx.x;

    const float* Kg = Kc + (size_t)kh * T_FULLC * HDC;
    const float* Vg = Vc + (size_t)kh * T_FULLC * HDC;

    // Load Q tile (pre-scaled)
    for (int i = tid; i < FBM * HDC / 4; i += 256) {
        int r = i >> 5;               // /32 float4s per row
        int d = (i & 31) << 2;
        float4 q4 = *(const float4*)(g_q + (size_t)(qbase + r) * HIDC + h * HDC + d);
        q4.x *= ATT_SCALE; q4.y *= ATT_SCALE; q4.z *= ATT_SCALE; q4.w *= ATT_SCALE;
        *(float4*)(Qs + r * 128 + d) = q4;
    }

    const int tr  = tid >> 4;           // 0..15
    const int tc  = tid & 15;           // 0..15
    const int r0  = tr * 4;             // 4 rows per thread (both stages)
    const int c0  = tc * 4;             // S-stage: 4 key cols
    const int d0  = tc * 8;             // PV-stage: 8 d-cols

    float m_i = -INFINITY, l_i = 0.f;   // per-row state, threads 0..63 own row=tid
    float acc[4][8];
    #pragma unroll
    for (int i = 0; i < 4; i++)
        #pragma unroll
        for (int j = 0; j < 8; j++) acc[i][j] = 0.f;

    const int nkt = (T_PASTC + qbase + FBM) / FBN;   // 33 + qi (exact)
    const int qpos0 = T_PASTC + qbase;

    for (int kt = 0; kt < nkt; kt++) {
        const int n0 = kt * FBN;
        __syncthreads();  // previous iteration's readers of Ks/Vs/Ss done
        // Load K/V tile
        for (int i = tid; i < FBM * HDC / 4; i += 256) {
            int r = i >> 5;
            int d = (i & 31) << 2;
            float4 k4 = *(const float4*)(Kg + (size_t)(n0 + r) * HDC + d);
            Ks[r*129 + d + 0] = k4.x;
            Ks[r*129 + d + 1] = k4.y;
            Ks[r*129 + d + 2] = k4.z;
            Ks[r*129 + d + 3] = k4.w;
            *(float4*)(Vs + r * 128 + d) = *(const float4*)(Vg + (size_t)(n0 + r) * HDC + d);
        }
        __syncthreads();

        // S = Q @ K^T  (4x4 per thread)
        float c[4][4];
        #pragma unroll
        for (int i = 0; i < 4; i++)
            #pragma unroll
            for (int j = 0; j < 4; j++) c[i][j] = 0.f;

        #pragma unroll 4
        for (int d = 0; d < HDC; d++) {
            float qr[4], kr[4];
            #pragma unroll
            for (int i = 0; i < 4; i++) qr[i] = Qs[(r0 + i) * 128 + d];
            #pragma unroll
            for (int j = 0; j < 4; j++) kr[j] = Ks[(c0 + j) * 129 + d];
            #pragma unroll
            for (int i = 0; i < 4; i++)
                #pragma unroll
                for (int j = 0; j < 4; j++)
                    c[i][j] += qr[i] * kr[j];
        }
        // write scores with causal mask
        #pragma unroll
        for (int i = 0; i < 4; i++) {
            const int qpos = qpos0 + r0 + i;
            #pragma unroll
            for (int j = 0; j < 4; j++) {
                const int kpos = n0 + c0 + j;
                Ss[(r0 + i) * 65 + c0 + j] = (kpos <= qpos) ? c[i][j] : -1e30f;
            }
        }
        __syncthreads();

        // Online softmax per row (threads 0..63)
        if (tid < FBM) {
            float mx = m_i;
            #pragma unroll 8
            for (int n = 0; n < FBN; n++) mx = fmaxf(mx, Ss[tid*65 + n]);
            const float f = __expf(m_i - mx);
            float sum = 0.f;
            #pragma unroll 8
            for (int n = 0; n < FBN; n++) {
                float p = __expf(Ss[tid*65 + n] - mx);
                Ss[tid*65 + n] = p;
                sum += p;
            }
            l_i = l_i * f + sum;
            m_i = mx;
            frow[tid] = f;
        }
        __syncthreads();

        // acc = acc*f + P @ V
        #pragma unroll
        for (int i = 0; i < 4; i++) {
            const float f = frow[r0 + i];
            #pragma unroll
            for (int j = 0; j < 8; j++) acc[i][j] *= f;
        }
        for (int n = 0; n < FBN; n++) {
            float vr[8];
            *(float4*)&vr[0] = *(const float4*)(Vs + n * 128 + d0);
            *(float4*)&vr[4] = *(const float4*)(Vs + n * 128 + d0 + 4);
            #pragma unroll
            for (int i = 0; i < 4; i++) {
                const float p = Ss[(r0 + i) * 65 + n];
                #pragma unroll
                for (int j = 0; j < 8; j++) acc[i][j] += p * vr[j];
            }
        }
    }

    if (tid < FBM) lrow[tid] = l_i;
    __syncthreads();

    #pragma unroll
    for (int i = 0; i < 4; i++) {
        const float inv = 1.f / lrow[r0 + i];
        const int row = qbase + r0 + i;
        float4 o1, o2;
        o1.x = acc[i][0]*inv; o1.y = acc[i][1]*inv; o1.z = acc[i][2]*inv; o1.w = acc[i][3]*inv;
        o2.x = acc[i][4]*inv; o2.y = acc[i][5]*inv; o2.z = acc[i][6]*inv; o2.w = acc[i][7]*inv;
        *(float4*)(g_attn + (size_t)row * HIDC + h * HDC + d0)     = o1;
        *(float4*)(g_attn + (size_t)row * HIDC + h * HDC + d0 + 4) = o2;
    }
}

// ---------------------------------------------------------------------------
// Launch
// ---------------------------------------------------------------------------
extern "C" void kernel_launch(void* const* d_in, const int* in_sizes, int n_in,
                              void* d_out, int out_size)
{
    const float* hs     = (const float*)d_in[0];
    // d_in[1] = attention_mask (exactly causal; handled analytically)
    const float* past_k = (const float*)d_in[2];
    const float* past_v = (const float*)d_in[3];
    const float* q_w    = (const float*)d_in[4];
    const float* q_b    = (const float*)d_in[5];
    const float* k_w    = (const float*)d_in[6];
    const float* k_b    = (const float*)d_in[7];
    const float* v_w    = (const float*)d_in[8];
    const float* v_b    = (const float*)d_in[9];
    const float* o_w    = (const float*)d_in[10];
    const float* o_b    = (const float*)d_in[11];
    float* out = (float*)d_out;

    float *gq, *gkn, *gvn, *gattn;
    cudaGetSymbolAddress((void**)&gq,    g_q);
    cudaGetSymbolAddress((void**)&gkn,   g_kn);
    cudaGetSymbolAddress((void**)&gvn,   g_vn);
    cudaGetSymbolAddress((void**)&gattn, g_attn);

    cudaFuncSetAttribute(flash_attn, cudaFuncAttributeMaxDynamicSharedMemorySize,
                         FSMEM_BYTES);

    // QKV projections
    sgemm_bias<<<dim3(HIDC/128, T_NEWC/128), 256>>>(hs, q_w, q_b, gq,  HIDC, HIDC);
    sgemm_bias<<<dim3(KVDC/128, T_NEWC/128), 256>>>(hs, k_w, k_b, gkn, KVDC, HIDC);
    sgemm_bias<<<dim3(KVDC/128, T_NEWC/128), 256>>>(hs, v_w, v_b, gvn, KVDC, HIDC);

    // KV-cache concat straight into output buffer
    {
        int total = KVHC * T_FULLC * HDC;
        concat_kv<<<(total + 255) / 256, 256>>>(past_k, past_v, out);
    }

    // Attention (reads K/V from the output cache regions)
    flash_attn<<<dim3(T_NEWC / FBM, NHC), 256, FSMEM_BYTES>>>(out + KOFF, out + VOFF);

    // Output projection
    sgemm_bias<<<dim3(HIDC/128, T_NEWC/128), 256>>>(gattn, o_w, o_b, out, HIDC, HIDC);
}

// round 2
// speedup vs baseline: 3.3635x; 3.3635x over previous
#include <cuda_runtime.h>
#include <cuda_bf16.h>
#include <math.h>

#define T_NEWC 2048
#define HIDC   2048
#define NHC    16
#define KVHC   2
#define HDC    128
#define T_PASTC 2048
#define T_FULLC 4096
#define KVDC   256

#define OUT0   (T_NEWC*HIDC)
#define KOFF   OUT0
#define VOFF   (OUT0 + KVHC*T_FULLC*HDC)

#define ATT_SCALE 0.08838834764831845f  // 1/sqrt(128)

// ---------------- scratch (static device globals) ----------------
__device__ float g_q[T_NEWC*HIDC];
__device__ float g_kn[T_NEWC*KVDC];
__device__ float g_vn[T_NEWC*KVDC];
__device__ float g_attn[T_NEWC*HIDC];

// bf16 hi/lo caches. uint4-typed for 16B alignment.
#define KV_HALVES (KVHC*T_FULLC*HDC)          // 1,048,576
__device__ uint4 g_khi4[KV_HALVES/8];
__device__ uint4 g_klo4[KV_HALVES/8];
__device__ uint4 g_vth4[KV_HALVES/8];         // V^T: [kh*128+d][4096] halves
__device__ uint4 g_vtl4[KV_HALVES/8];

// ---------------- helpers ----------------
__device__ __forceinline__ unsigned pack_bf2(__nv_bfloat16 a, __nv_bfloat16 b) {
    __nv_bfloat162 t = __halves2bfloat162(a, b);   // .x = a (low 16 bits)
    return *reinterpret_cast<unsigned*>(&t);
}
// hi/lo bf16 split of two floats, packed as mma operands
__device__ __forceinline__ void split2(float x, float y, unsigned& hi, unsigned& lo) {
    __nv_bfloat16 xh = __float2bfloat16_rn(x);
    __nv_bfloat16 yh = __float2bfloat16_rn(y);
    __nv_bfloat16 xl = __float2bfloat16_rn(x - __bfloat162float(xh));
    __nv_bfloat16 yl = __float2bfloat16_rn(y - __bfloat162float(yh));
    hi = pack_bf2(xh, yh);
    lo = pack_bf2(xl, yl);
}
__device__ __forceinline__ void mma_bf16(float* c, const unsigned* a, unsigned b0, unsigned b1) {
    asm volatile(
        "mma.sync.aligned.m16n8k16.row.col.f32.bf16.bf16.f32 "
        "{%0,%1,%2,%3}, {%4,%5,%6,%7}, {%8,%9}, {%0,%1,%2,%3};\n"
        : "+f"(c[0]), "+f"(c[1]), "+f"(c[2]), "+f"(c[3])
        : "r"(a[0]), "r"(a[1]), "r"(a[2]), "r"(a[3]), "r"(b0), "r"(b1));
}

// ---------------------------------------------------------------------------
// GEMM (bf16x3): C[M,N] = A[M,K] @ W[N,K]^T + bias.  128x128 tile, BK=32,
// 4 warps (2x2), warp tile 64x64.
// ---------------------------------------------------------------------------
__global__ __launch_bounds__(128, 2) void gemm_bf16x3(
    const float* __restrict__ A, const float* __restrict__ W,
    const float* __restrict__ bias, float* __restrict__ C,
    int N, int K)
{
    __shared__ unsigned short Ah[128*40], Al[128*40], Bh[128*40], Bl[128*40];

    const int tid  = threadIdx.x;
    const int w    = tid >> 5;
    const int lane = tid & 31;
    const int g    = lane >> 2;
    const int tig  = lane & 3;
    const int wm   = w >> 1, wn = w & 1;
    const int bm   = blockIdx.y * 128;
    const int bn   = blockIdx.x * 128;

    float acc[4][8][4];
    #pragma unroll
    for (int mt = 0; mt < 4; mt++)
        #pragma unroll
        for (int nt = 0; nt < 8; nt++)
            #pragma unroll
            for (int c = 0; c < 4; c++) acc[mt][nt][c] = 0.f;

    for (int k0 = 0; k0 < K; k0 += 32) {
        __syncthreads();
        // load + split A and W tiles (128 rows x 32 k each)
        #pragma unroll
        for (int it = 0; it < 8; it++) {
            int i = tid + it * 128;          // 0..1023
            int row = i >> 3, seg = i & 7;   // col = seg*4
            int col = seg * 4;
            float4 a = *(const float4*)(A + (size_t)(bm + row) * K + k0 + col);
            unsigned h0, l0, h1, l1;
            split2(a.x, a.y, h0, l0);
            split2(a.z, a.w, h1, l1);
            *(uint2*)(Ah + row*40 + col) = make_uint2(h0, h1);
            *(uint2*)(Al + row*40 + col) = make_uint2(l0, l1);
            float4 b = *(const float4*)(W + (size_t)(bn + row) * K + k0 + col);
            split2(b.x, b.y, h0, l0);
            split2(b.z, b.w, h1, l1);
            *(uint2*)(Bh + row*40 + col) = make_uint2(h0, h1);
            *(uint2*)(Bl + row*40 + col) = make_uint2(l0, l1);
        }
        __syncthreads();

        #pragma unroll
        for (int kc = 0; kc < 32; kc += 16) {
            unsigned ah[4][4], al[4][4];
            #pragma unroll
            for (int mt = 0; mt < 4; mt++) {
                int rb = wm*64 + mt*16 + g;
                ah[mt][0] = *(const unsigned*)(Ah + rb*40 + kc + 2*tig);
                ah[mt][1] = *(const unsigned*)(Ah + (rb+8)*40 + kc + 2*tig);
                ah[mt][2] = *(const unsigned*)(Ah + rb*40 + kc + 2*tig + 8);
                ah[mt][3] = *(const unsigned*)(Ah + (rb+8)*40 + kc + 2*tig + 8);
                al[mt][0] = *(const unsigned*)(Al + rb*40 + kc + 2*tig);
                al[mt][1] = *(const unsigned*)(Al + (rb+8)*40 + kc + 2*tig);
                al[mt][2] = *(const unsigned*)(Al + rb*40 + kc + 2*tig + 8);
                al[mt][3] = *(const unsigned*)(Al + (rb+8)*40 + kc + 2*tig + 8);
            }
            #pragma unroll
            for (int nt = 0; nt < 8; nt++) {
                int cr = wn*64 + nt*8 + g;
                unsigned bh0 = *(const unsigned*)(Bh + cr*40 + kc + 2*tig);
                unsigned bh1 = *(const unsigned*)(Bh + cr*40 + kc + 2*tig + 8);
                unsigned bl0 = *(const unsigned*)(Bl + cr*40 + kc + 2*tig);
                unsigned bl1 = *(const unsigned*)(Bl + cr*40 + kc + 2*tig + 8);
                #pragma unroll
                for (int mt = 0; mt < 4; mt++) {
                    mma_bf16(acc[mt][nt], ah[mt], bh0, bh1);
                    mma_bf16(acc[mt][nt], ah[mt], bl0, bl1);
                    mma_bf16(acc[mt][nt], al[mt], bh0, bh1);
                }
            }
        }
    }

    // epilogue
    #pragma unroll
    for (int mt = 0; mt < 4; mt++) {
        #pragma unroll
        for (int nt = 0; nt < 8; nt++) {
            int row = bm + wm*64 + mt*16 + g;
            int col = bn + wn*64 + nt*8 + 2*tig;
            float b0 = bias[col], b1 = bias[col+1];
            float2 v0 = make_float2(acc[mt][nt][0] + b0, acc[mt][nt][1] + b1);
            float2 v1 = make_float2(acc[mt][nt][2] + b0, acc[mt][nt][3] + b1);
            *(float2*)(C + (size_t)row * N + col) = v0;
            *(float2*)(C + (size_t)(row + 8) * N + col) = v1;
        }
    }
}

// ---------------------------------------------------------------------------
// prep_kv: concat cache -> out (fp32), and build bf16 hi/lo K cache +
// transposed V cache. Block = (t-tile of 64, kv-head). 256 threads.
// ---------------------------------------------------------------------------
__global__ __launch_bounds__(256) void prep_kv(
    const float* __restrict__ pk, const float* __restrict__ pv,
    float* __restrict__ out)
{
    __shared__ float Vsm[64][129];
    const int tid = threadIdx.x;
    const int h   = blockIdx.y;
    const int t0  = blockIdx.x * 64;

    uint2* khi = (uint2*)g_khi4;
    uint2* klo = (uint2*)g_klo4;
    uint2* vth = (uint2*)g_vth4;
    uint2* vtl = (uint2*)g_vtl4;

    #pragma unroll
    for (int it = 0; it < 8; it++) {
        int i = tid + it * 256;        // 0..2047 float4s
        int row = i >> 5, seg = i & 31;
        int t = t0 + row, d = seg * 4;
        float4 k4, v4;
        if (t < T_PASTC) {
            size_t src = ((size_t)h * T_PASTC + t) * HDC + d;
            k4 = *(const float4*)(pk + src);
            v4 = *(const float4*)(pv + src);
        } else {
            size_t src = (size_t)(t - T_PASTC) * KVDC + h * HDC + d;
            k4 = *(const float4*)(g_kn + src);
            v4 = *(const float4*)(g_vn + src);
        }
        size_t oidx = ((size_t)h * T_FULLC + t) * HDC + d;
        *(float4*)(out + KOFF + oidx) = k4;
        *(float4*)(out + VOFF + oidx) = v4;
        unsigned h0, l0, h1, l1;
        split2(k4.x, k4.y, h0, l0);
        split2(k4.z, k4.w, h1, l1);
        khi[oidx >> 2] = make_uint2(h0, h1);
        klo[oidx >> 2] = make_uint2(l0, l1);
        Vsm[row][d]   = v4.x; Vsm[row][d+1] = v4.y;
        Vsm[row][d+2] = v4.z; Vsm[row][d+3] = v4.w;
    }
    __syncthreads();

    // transposed V: [h*128+d][t]
    #pragma unroll
    for (int it = 0; it < 16; it++) {
        int i = tid + it * 256;        // 0..4095
        int split = i >> 11;
        int d = (i >> 4) & 127;
        int seg = i & 15;
        int tl = seg * 4;
        float v0 = Vsm[tl+0][d], v1 = Vsm[tl+1][d], v2 = Vsm[tl+2][d], v3 = Vsm[tl+3][d];
        unsigned h0, l0, h1, l1;
        split2(v0, v1, h0, l0);
        split2(v2, v3, h1, l1);
        size_t oidx = ((size_t)(h*128 + d) * T_FULLC + t0 + tl) >> 2;
        if (split == 0) vth[oidx] = make_uint2(h0, h1);
        else            vtl[oidx] = make_uint2(l0, l1);
    }
}

// ---------------------------------------------------------------------------
// Flash attention, bf16x3 on tensor cores. BM=64, BN=64, 4 warps.
// Warp w owns rows w*16..w*16+15. Softmax fully in registers (FA2 layout).
// ---------------------------------------------------------------------------
#define FSMEM_HALVES (4*64*136 + 2*128*72)    // 53248
#define FSMEM_BYTES  (FSMEM_HALVES * 2)       // 106496

__global__ __launch_bounds__(128, 2) void flash_bf16x3()
{
    extern __shared__ unsigned short fsm[];
    unsigned short* Qh  = fsm;
    unsigned short* Ql  = Qh  + 64*136;
    unsigned short* Kh  = Ql  + 64*136;
    unsigned short* Kl  = Kh  + 64*136;
    unsigned short* Vth = Kl  + 64*136;
    unsigned short* Vtl = Vth + 128*72;

    const int tid  = threadIdx.x;
    const int w    = tid >> 5;
    const int lane = tid & 31;
    const int g    = lane >> 2;
    const int tig  = lane & 3;
    const int qi = blockIdx.x;
    const int h  = blockIdx.y;
    const int qbase = qi * 64;
    const int kh = h >> 3;

    // ---- load + split Q tile (scaled) ----
    #pragma unroll
    for (int it = 0; it < 16; it++) {
        int i = tid + it * 128;        // 0..2047 float4s
        int row = i >> 5, seg = i & 31;
        int d = seg * 4;
        float4 q4 = *(const float4*)(g_q + (size_t)(qbase + row) * HIDC + h * HDC + d);
        q4.x *= ATT_SCALE; q4.y *= ATT_SCALE; q4.z *= ATT_SCALE; q4.w *= ATT_SCALE;
        unsigned h0, l0, h1, l1;
        split2(q4.x, q4.y, h0, l0);
        split2(q4.z, q4.w, h1, l1);
        *(uint2*)(Qh + row*136 + d) = make_uint2(h0, h1);
        *(uint2*)(Ql + row*136 + d) = make_uint2(l0, l1);
    }

    float accO[16][4];
    #pragma unroll
    for (int dt = 0; dt < 16; dt++)
        #pragma unroll
        for (int c = 0; c < 4; c++) accO[dt][c] = 0.f;
    float m0 = -INFINITY, m1 = -INFINITY, l0s = 0.f, l1s = 0.f;

    const int nkt = 33 + qi;
    const uint4* Ksrc_h = g_khi4;
    const uint4* Ksrc_l = g_klo4;
    const uint4* Vsrc_h = g_vth4;
    const uint4* Vsrc_l = g_vtl4;

    for (int kt = 0; kt < nkt; kt++) {
        const int n0 = kt * 64;
        __syncthreads();
        // K tiles: 64 keys x 128 d halves, hi+lo = 2048 uint4
        #pragma unroll
        for (int it = 0; it < 16; it++) {
            int i = tid + it * 128;
            int split = i >> 10;
            int j = i & 1023;
            int row = j >> 4, seg = j & 15;
            size_t src = ((size_t)(kh * T_FULLC + n0 + row) << 4) + seg;
            uint4 v = split ? Ksrc_l[src] : Ksrc_h[src];
            unsigned short* dst = split ? Kl : Kh;
            *(uint4*)(dst + row*136 + seg*8) = v;
        }
        // V^T tiles: 128 d x 64 keys halves, hi+lo = 2048 uint4
        #pragma unroll
        for (int it = 0; it < 16; it++) {
            int i = tid + it * 128;
            int split = i >> 10;
            int j = i & 1023;
            int row = j >> 3, seg = j & 7;
            size_t src = ((size_t)(kh * 128 + row) << 9) + (n0 >> 3) + seg;
            uint4 v = split ? Vsrc_l[src] : Vsrc_h[src];
            unsigned short* dst = split ? Vtl : Vth;
            *(uint4*)(dst + row*72 + seg*8) = v;
        }
        __syncthreads();

        // ---- S = Q K^T ----
        float s[8][4];
        #pragma unroll
        for (int nt = 0; nt < 8; nt++)
            #pragma unroll
            for (int c = 0; c < 4; c++) s[nt][c] = 0.f;

        #pragma unroll
        for (int kc8 = 0; kc8 < 8; kc8++) {
            const int kc = kc8 * 16;
            unsigned qh[4], ql[4];
            int rb = w*16 + g;
            qh[0] = *(const unsigned*)(Qh + rb*136 + kc + 2*tig);
            qh[1] = *(const unsigned*)(Qh + (rb+8)*136 + kc + 2*tig);
            qh[2] = *(const unsigned*)(Qh + rb*136 + kc + 2*tig + 8);
            qh[3] = *(const unsigned*)(Qh + (rb+8)*136 + kc + 2*tig + 8);
            ql[0] = *(const unsigned*)(Ql + rb*136 + kc + 2*tig);
            ql[1] = *(const unsigned*)(Ql + (rb+8)*136 + kc + 2*tig);
            ql[2] = *(const unsigned*)(Ql + rb*136 + kc + 2*tig + 8);
            ql[3] = *(const unsigned*)(Ql + (rb+8)*136 + kc + 2*tig + 8);
            #pragma unroll
            for (int nt = 0; nt < 8; nt++) {
                int kr = nt*8 + g;
                unsigned bh0 = *(const unsigned*)(Kh + kr*136 + kc + 2*tig);
                unsigned bh1 = *(const unsigned*)(Kh + kr*136 + kc + 2*tig + 8);
                unsigned bl0 = *(const unsigned*)(Kl + kr*136 + kc + 2*tig);
                unsigned bl1 = *(const unsigned*)(Kl + kr*136 + kc + 2*tig + 8);
                mma_bf16(s[nt], qh, bh0, bh1);
                mma_bf16(s[nt], qh, bl0, bl1);
                mma_bf16(s[nt], ql, bh0, bh1);
            }
        }

        // ---- causal mask (only diagonal tile) ----
        if (kt == nkt - 1) {
            int r0 = w*16 + g, r1 = r0 + 8;
            #pragma unroll
            for (int nt = 0; nt < 8; nt++) {
                int cb = nt*8 + 2*tig;
                if (cb     > r0) s[nt][0] = -1e30f;
                if (cb + 1 > r0) s[nt][1] = -1e30f;
                if (cb     > r1) s[nt][2] = -1e30f;
                if (cb + 1 > r1) s[nt][3] = -1e30f;
            }
        }

        // ---- online softmax (registers) ----
        float mx0 = -1e30f, mx1 = -1e30f;
        #pragma unroll
        for (int nt = 0; nt < 8; nt++) {
            mx0 = fmaxf(mx0, fmaxf(s[nt][0], s[nt][1]));
            mx1 = fmaxf(mx1, fmaxf(s[nt][2], s[nt][3]));
        }
        mx0 = fmaxf(mx0, __shfl_xor_sync(0xffffffffu, mx0, 1));
        mx0 = fmaxf(mx0, __shfl_xor_sync(0xffffffffu, mx0, 2));
        mx1 = fmaxf(mx1, __shfl_xor_sync(0xffffffffu, mx1, 1));
        mx1 = fmaxf(mx1, __shfl_xor_sync(0xffffffffu, mx1, 2));
        float mn0 = fmaxf(m0, mx0), mn1 = fmaxf(m1, mx1);
        float f0 = __expf(m0 - mn0), f1 = __expf(m1 - mn1);
        float sum0 = 0.f, sum1 = 0.f;
        #pragma unroll
        for (int nt = 0; nt < 8; nt++) {
            s[nt][0] = __expf(s[nt][0] - mn0); sum0 += s[nt][0];
            s[nt][1] = __expf(s[nt][1] - mn0); sum0 += s[nt][1];
            s[nt][2] = __expf(s[nt][2] - mn1); sum1 += s[nt][2];
            s[nt][3] = __expf(s[nt][3] - mn1); sum1 += s[nt][3];
        }
        sum0 += __shfl_xor_sync(0xffffffffu, sum0, 1);
        sum0 += __shfl_xor_sync(0xffffffffu, sum0, 2);
        sum1 += __shfl_xor_sync(0xffffffffu, sum1, 1);
        sum1 += __shfl_xor_sync(0xffffffffu, sum1, 2);
        l0s = l0s * f0 + sum0;
        l1s = l1s * f1 + sum1;
        m0 = mn0; m1 = mn1;

        #pragma unroll
        for (int dt = 0; dt < 16; dt++) {
            accO[dt][0] *= f0; accO[dt][1] *= f0;
            accO[dt][2] *= f1; accO[dt][3] *= f1;
        }

        // ---- convert P to bf16 hi/lo A-fragments ----
        unsigned phi[4][4], plo[4][4];
        #pragma unroll
        for (int kc2 = 0; kc2 < 4; kc2++) {
            split2(s[2*kc2][0],   s[2*kc2][1],   phi[kc2][0], plo[kc2][0]);
            split2(s[2*kc2][2],   s[2*kc2][3],   phi[kc2][1], plo[kc2][1]);
            split2(s[2*kc2+1][0], s[2*kc2+1][1], phi[kc2][2], plo[kc2][2]);
            split2(s[2*kc2+1][2], s[2*kc2+1][3], phi[kc2][3], plo[kc2][3]);
        }

        // ---- O += P V ----
        #pragma unroll
        for (int dt = 0; dt < 16; dt++) {
            int vr = dt*8 + g;
            #pragma unroll
            for (int kc2 = 0; kc2 < 4; kc2++) {
                unsigned vh0 = *(const unsigned*)(Vth + vr*72 + kc2*16 + 2*tig);
                unsigned vh1 = *(const unsigned*)(Vth + vr*72 + kc2*16 + 2*tig + 8);
                unsigned vl0 = *(const unsigned*)(Vtl + vr*72 + kc2*16 + 2*tig);
                unsigned vl1 = *(const unsigned*)(Vtl + vr*72 + kc2*16 + 2*tig + 8);
                mma_bf16(accO[dt], phi[kc2], vh0, vh1);
                mma_bf16(accO[dt], phi[kc2], vl0, vl1);
                mma_bf16(accO[dt], plo[kc2], vh0, vh1);
            }
        }
    }

    // ---- epilogue ----
    float inv0 = 1.f / l0s, inv1 = 1.f / l1s;
    int row0 = qbase + w*16 + g;
    #pragma unroll
    for (int dt = 0; dt < 16; dt++) {
        int col = h * HDC + dt*8 + 2*tig;
        float2 o0 = make_float2(accO[dt][0] * inv0, accO[dt][1] * inv0);
        float2 o1 = make_float2(accO[dt][2] * inv1, accO[dt][3] * inv1);
        *(float2*)(g_attn + (size_t)row0 * HIDC + col) = o0;
        *(float2*)(g_attn + (size_t)(row0 + 8) * HIDC + col) = o1;
    }
}

// ---------------------------------------------------------------------------
extern "C" void kernel_launch(void* const* d_in, const int* in_sizes, int n_in,
                              void* d_out, int out_size)
{
    const float* hs     = (const float*)d_in[0];
    const float* past_k = (const float*)d_in[2];
    const float* past_v = (const float*)d_in[3];
    const float* q_w    = (const float*)d_in[4];
    const float* q_b    = (const float*)d_in[5];
    const float* k_w    = (const float*)d_in[6];
    const float* k_b    = (const float*)d_in[7];
    const float* v_w    = (const float*)d_in[8];
    const float* v_b    = (const float*)d_in[9];
    const float* o_w    = (const float*)d_in[10];
    const float* o_b    = (const float*)d_in[11];
    float* out = (float*)d_out;

    float *gq, *gkn, *gvn, *gattn;
    cudaGetSymbolAddress((void**)&gq,    g_q);
    cudaGetSymbolAddress((void**)&gkn,   g_kn);
    cudaGetSymbolAddress((void**)&gvn,   g_vn);
    cudaGetSymbolAddress((void**)&gattn, g_attn);

    cudaFuncSetAttribute(flash_bf16x3, cudaFuncAttributeMaxDynamicSharedMemorySize,
                         FSMEM_BYTES);

    // projections
    gemm_bf16x3<<<dim3(HIDC/128, T_NEWC/128), 128>>>(hs, q_w, q_b, gq,  HIDC, HIDC);
    gemm_bf16x3<<<dim3(KVDC/128, T_NEWC/128), 128>>>(hs, k_w, k_b, gkn, KVDC, HIDC);
    gemm_bf16x3<<<dim3(KVDC/128, T_NEWC/128), 128>>>(hs, v_w, v_b, gvn, KVDC, HIDC);

    // concat + bf16 split + V transpose
    prep_kv<<<dim3(T_FULLC/64, KVHC), 256>>>(past_k, past_v, out);

    // attention
    flash_bf16x3<<<dim3(T_NEWC/64, NHC), 128, FSMEM_BYTES>>>();

    // output projection
    gemm_bf16x3<<<dim3(HIDC/128, T_NEWC/128), 128>>>(gattn, o_w, o_b, out, HIDC, HIDC);
}